// round 3
// baseline (speedup 1.0000x reference)
#include <cuda_runtime.h>

#define Nn   50000
#define Ee   800000
#define DIN  128
#define DH   256
#define DOUT 128
#define BNEPS 1e-5f

// ---------------- scratch (device globals: allocation-free) ----------------
__device__ int   g_is64;
__device__ __align__(256) int   g_src [Ee];
__device__ __align__(256) int   g_dst [Ee];
__device__ __align__(256) float g_nrm [Ee];
__device__ __align__(256) float g_deg [Nn];
__device__ __align__(256) float g_dinv[Nn];
__device__ __align__(256) float g_bufA[(size_t)Nn * DH];
__device__ __align__(256) float g_bufB[(size_t)Nn * DH];
__device__ __align__(256) float g_bufC[(size_t)Nn * DH];
__device__ __align__(256) float g_sum  [DH];
__device__ __align__(256) float g_sumsq[DH];
__device__ __align__(256) float g_scale[DH];
__device__ __align__(256) float g_shift[DH];

// ---------------- edge-index dtype detect + convert ----------------
// int64 nonneg values have hi word == 0 for all elements; int32 data has
// random edge values in those positions.
__global__ void k_detect(const uint2* __restrict__ ei) {
    if (threadIdx.x == 0 && blockIdx.x == 0) {
        int is64 = 1;
        for (int i = 0; i < 64; i++)
            if (ei[i].y != 0u) { is64 = 0; break; }
        g_is64 = is64;
    }
}

__global__ void k_convert(const void* __restrict__ ei) {
    int e = blockIdx.x * blockDim.x + threadIdx.x;
    if (e >= Ee) return;
    int s, d;
    if (g_is64) {
        const long long* p = (const long long*)ei;
        s = (int)p[e];
        d = (int)p[e + Ee];
    } else {
        const int* p = (const int*)ei;
        s = p[e];
        d = p[e + Ee];
    }
    g_src[e] = min(max(s, 0), Nn - 1);
    g_dst[e] = min(max(d, 0), Nn - 1);
}

// ---------------- degree / normalization ----------------
__global__ void k_deg_init() {
    int i = blockIdx.x * blockDim.x + threadIdx.x;
    if (i < Nn) g_deg[i] = 1.0f;               // self loop contributes 1
}

__global__ void k_deg_acc() {
    int e = blockIdx.x * blockDim.x + threadIdx.x;
    if (e < Ee) atomicAdd(&g_deg[g_dst[e]], 1.0f);
}

__global__ void k_dinv() {
    int i = blockIdx.x * blockDim.x + threadIdx.x;
    if (i < Nn) g_dinv[i] = rsqrtf(g_deg[i]);
}

__global__ void k_edge_nrm() {
    int e = blockIdx.x * blockDim.x + threadIdx.x;
    if (e < Ee) g_nrm[e] = g_dinv[g_src[e]] * g_dinv[g_dst[e]];
}

// ---------------- aggregation: init with self-loop term ----------------
template<int F>
__global__ void k_self_init(const float* __restrict__ in, float* __restrict__ out) {
    int idx = blockIdx.x * blockDim.x + threadIdx.x;     // over Nn*F/4
    if (idx >= Nn * (F / 4)) return;
    int row = idx / (F / 4);
    float s = g_dinv[row]; s = s * s;
    float4 v = ((const float4*)in)[idx];
    v.x *= s; v.y *= s; v.z *= s; v.w *= s;
    ((float4*)out)[idx] = v;
}

// one warp per edge; F floats lane-strided (coalesced), scalar REDG.ADD.F32
template<int F>
__global__ void k_scatter(const float* __restrict__ in, float* __restrict__ out) {
    int e = (blockIdx.x * blockDim.x + threadIdx.x) >> 5;
    if (e >= Ee) return;
    int lane = threadIdx.x & 31;
    int s = g_src[e];
    int d = g_dst[e];
    float nrm = g_nrm[e];
    const float* rin  = in  + (size_t)s * F;
    float*       rout = out + (size_t)d * F;
#pragma unroll
    for (int j = lane; j < F; j += 32) {
        atomicAdd(&rout[j], __ldg(&rin[j]) * nrm);
    }
}

// ---------------- BatchNorm ----------------
__global__ void k_bn_zero() {
    int f = threadIdx.x;
    if (f < DH) { g_sum[f] = 0.0f; g_sumsq[f] = 0.0f; }
}

template<int F, int RPB>
__global__ void k_bn_stats(const float* __restrict__ h) {
    int f  = threadIdx.x;                // F threads per block
    int r0 = blockIdx.x * RPB;
    int r1 = min(r0 + RPB, Nn);
    float s = 0.0f, ss = 0.0f;
    for (int r = r0; r < r1; ++r) {
        float v = h[(size_t)r * F + f];
        s += v; ss += v * v;
    }
    atomicAdd(&g_sum[f],   s);
    atomicAdd(&g_sumsq[f], ss);
}

__global__ void k_bn_final(const float* __restrict__ g, const float* __restrict__ be) {
    int f = threadIdx.x;
    if (f >= DH) return;
    float mu  = g_sum[f]   * (1.0f / Nn);
    float var = g_sumsq[f] * (1.0f / Nn) - mu * mu;
    float sc  = g[f] * rsqrtf(var + BNEPS);
    g_scale[f] = sc;
    g_shift[f] = be[f] - mu * sc;
}

template<bool RES>
__global__ void k_bn_apply(const float* __restrict__ h,
                           const float* __restrict__ res,
                           float* __restrict__ out) {
    int idx = blockIdx.x * blockDim.x + threadIdx.x;     // over Nn*DH/4
    if (idx >= Nn * (DH / 4)) return;
    int f4 = idx & (DH / 4 - 1);
    float4 v  = ((const float4*)h)[idx];
    float4 sc = ((const float4*)g_scale)[f4];
    float4 sh = ((const float4*)g_shift)[f4];
    v.x = fmaxf(v.x * sc.x + sh.x, 0.0f);
    v.y = fmaxf(v.y * sc.y + sh.y, 0.0f);
    v.z = fmaxf(v.z * sc.z + sh.z, 0.0f);
    v.w = fmaxf(v.w * sc.w + sh.w, 0.0f);
    if (RES) {
        float4 r = ((const float4*)res)[idx];
        v.x += r.x; v.y += r.y; v.z += r.z; v.w += r.w;
    }
    ((float4*)out)[idx] = v;
}

// ---------------- final layer epilogue init: M2*dinv^2 + b2 + x ----------------
__global__ void k_final_init(const float* __restrict__ m2,
                             const float* __restrict__ x,
                             const float* __restrict__ b2,
                             float* __restrict__ out) {
    int idx = blockIdx.x * blockDim.x + threadIdx.x;     // over Nn*DOUT/4
    if (idx >= Nn * (DOUT / 4)) return;
    int row = idx / (DOUT / 4);
    int c4  = idx & (DOUT / 4 - 1);
    float s = g_dinv[row]; s = s * s;
    float4 m = ((const float4*)m2)[idx];
    float4 xx = ((const float4*)x)[idx];
    float4 b  = ((const float4*)b2)[c4];
    m.x = m.x * s + xx.x + b.x;
    m.y = m.y * s + xx.y + b.y;
    m.z = m.z * s + xx.z + b.z;
    m.w = m.w * s + xx.w + b.w;
    ((float4*)out)[idx] = m;
}

// ---------------- SGEMM: C[MxNc] = A[MxK] * B[KxNc], row-major ----------------
// BM=BN=128, BK=8, 256 threads, 8x8 per thread. Nc multiple of 128, K multiple of 8.
__global__ void __launch_bounds__(256)
k_sgemm(int M, int Nc, int K,
        const float* __restrict__ A, const float* __restrict__ B, float* __restrict__ C) {
    constexpr int BM = 128, BN = 128, BK = 8, TM = 8, TN = 8;
    __shared__ float As[BK][BM];
    __shared__ float Bs[BK][BN];
    int tid  = threadIdx.x;
    int brow = blockIdx.y * BM;
    int bcol = blockIdx.x * BN;
    int trow = (tid / (BN / TN)) * TM;   // tid/16*8
    int tcol = (tid % (BN / TN)) * TN;   // tid%16*8

    int aRow = tid >> 1;                 // 0..127
    int aCol = (tid & 1) * 4;            // 0 or 4
    int bRow = tid >> 5;                 // 0..7
    int bCol = (tid & 31) * 4;

    float acc[TM][TN];
#pragma unroll
    for (int i = 0; i < TM; i++)
#pragma unroll
        for (int j = 0; j < TN; j++) acc[i][j] = 0.0f;

    for (int k0 = 0; k0 < K; k0 += BK) {
        float4 a4;
        int gr = brow + aRow;
        if (gr < M) a4 = *(const float4*)(A + (size_t)gr * K + k0 + aCol);
        else        a4 = make_float4(0.f, 0.f, 0.f, 0.f);
        As[aCol + 0][aRow] = a4.x;
        As[aCol + 1][aRow] = a4.y;
        As[aCol + 2][aRow] = a4.z;
        As[aCol + 3][aRow] = a4.w;
        *(float4*)&Bs[bRow][bCol] =
            *(const float4*)(B + (size_t)(k0 + bRow) * Nc + bcol + bCol);
        __syncthreads();
#pragma unroll
        for (int kk = 0; kk < BK; kk++) {
            float4 a0 = *(float4*)&As[kk][trow];
            float4 a1 = *(float4*)&As[kk][trow + 4];
            float4 b0 = *(float4*)&Bs[kk][tcol];
            float4 b1 = *(float4*)&Bs[kk][tcol + 4];
            float ar[TM] = {a0.x, a0.y, a0.z, a0.w, a1.x, a1.y, a1.z, a1.w};
            float br[TN] = {b0.x, b0.y, b0.z, b0.w, b1.x, b1.y, b1.z, b1.w};
#pragma unroll
            for (int i = 0; i < TM; i++)
#pragma unroll
                for (int j = 0; j < TN; j++)
                    acc[i][j] = fmaf(ar[i], br[j], acc[i][j]);
        }
        __syncthreads();
    }
#pragma unroll
    for (int i = 0; i < TM; i++) {
        int gr = brow + trow + i;
        if (gr >= M) continue;
#pragma unroll
        for (int j = 0; j < TN; j += 4) {
            float4 v = make_float4(acc[i][j], acc[i][j + 1], acc[i][j + 2], acc[i][j + 3]);
            *(float4*)(C + (size_t)gr * Nc + bcol + tcol + j) = v;
        }
    }
}

// ---------------- launch ----------------
extern "C" void kernel_launch(void* const* d_in, const int* in_sizes, int n_in,
                              void* d_out, int out_size) {
    const float* x  = (const float*)d_in[0];
    const void*  ei = d_in[1];
    const float* W0 = (const float*)d_in[2];
    // b0 = d_in[3]  (cancels exactly through BatchNorm)
    const float* g0  = (const float*)d_in[4];
    const float* be0 = (const float*)d_in[5];
    const float* W1  = (const float*)d_in[6];
    // b1 = d_in[7]  (cancels exactly through BatchNorm)
    const float* g1  = (const float*)d_in[8];
    const float* be1 = (const float*)d_in[9];
    const float* W2  = (const float*)d_in[10];
    const float* b2  = (const float*)d_in[11];
    float* out = (float*)d_out;

    float *bufA, *bufB, *bufC;
    cudaGetSymbolAddress((void**)&bufA, g_bufA);
    cudaGetSymbolAddress((void**)&bufB, g_bufB);
    cudaGetSymbolAddress((void**)&bufC, g_bufC);

    const int TB = 256;
    int gridE1 = (Ee + TB - 1) / TB;

    // edge-index dtype detect + convert + normalization
    k_detect  <<<1, 32>>>((const uint2*)ei);
    k_convert <<<gridE1, TB>>>(ei);
    k_deg_init<<<(Nn + TB - 1) / TB, TB>>>();
    k_deg_acc <<<gridE1, TB>>>();
    k_dinv    <<<(Nn + TB - 1) / TB, TB>>>();
    k_edge_nrm<<<gridE1, TB>>>();

    int gridN128 = (Nn * (DIN / 4) + TB - 1) / TB;   // Nn*32 f4
    int gridN256 = (Nn * (DH  / 4) + TB - 1) / TB;   // Nn*64 f4
    int gridE    = (Ee * 32 + TB - 1) / TB;          // 1 warp / edge

    // ---- layer 0: aggregate-first on x (128-dim) ----
    k_self_init<DIN><<<gridN128, TB>>>(x, bufA);
    k_scatter<DIN>  <<<gridE, TB>>>(x, bufA);
    {
        dim3 g(DH / 128, (Nn + 127) / 128);
        k_sgemm<<<g, 256>>>(Nn, DH, DIN, bufA, W0, bufB);     // H0 = (A x) W0
    }
    k_bn_zero<<<1, 256>>>();
    k_bn_stats<DH, 64><<<(Nn + 63) / 64, DH>>>(bufB);
    k_bn_final<<<1, 256>>>(g0, be0);
    k_bn_apply<false><<<gridN256, TB>>>(bufB, nullptr, bufA);  // h1 -> bufA

    // ---- layer 1: aggregate-first on h1 (256-dim) ----
    k_self_init<DH><<<gridN256, TB>>>(bufA, bufC);
    k_scatter<DH>  <<<gridE, TB>>>(bufA, bufC);
    {
        dim3 g(DH / 128, (Nn + 127) / 128);
        k_sgemm<<<g, 256>>>(Nn, DH, DH, bufC, W1, bufB);       // M1 = (A h1) W1
    }
    k_bn_zero<<<1, 256>>>();
    k_bn_stats<DH, 64><<<(Nn + 63) / 64, DH>>>(bufB);
    k_bn_final<<<1, 256>>>(g1, be1);
    k_bn_apply<true><<<gridN256, TB>>>(bufB, bufA, bufC);      // h2 = relu(bn)+h1 -> bufC

    // ---- layer 2: transform-first (128-dim scatter), fused +b2 +x residual ----
    {
        dim3 g(DOUT / 128, (Nn + 127) / 128);
        k_sgemm<<<g, 256>>>(Nn, DOUT, DH, bufC, W2, bufA);     // M2 = h2 W2
    }
    k_final_init<<<gridN128, TB>>>(bufA, x, b2, out);          // M2*dinv^2 + b2 + x
    k_scatter<DOUT><<<gridE, TB>>>(bufA, out);
}